// round 1
// baseline (speedup 1.0000x reference)
#include <cuda_runtime.h>

// CapsuleLayer dynamic routing, fused recompute formulation.
//
// Shapes: u [B=32, N=2048, K=16] f32, W [N=2048, K=16, OUTC=1024] f32,
// out [B=32, NCAP=32, DCAP=32] f32.
//
// Passes (each streams W once, recomputing u_hat tiles on the fly):
//   P0 (mode 0): o0 = (1/32) * sum_n u_hat[b,n,:]          (uniform softmax of b=0)
//   R  (mode 0): reduce partials, l2-normalize            -> g_o
//   P1 (mode 1): per n: b = o_prev . u_hat[:,n,:], softmax over capsules (local
//                in n!), accumulate c * u_hat into o partials
//   R  (mode 1): reduce, l2-normalize                      -> g_o
//   P1 (mode 1) again
//   R  (mode 2): reduce, squash                            -> d_out

#define BB    32
#define NN    2048
#define KK    16
#define NCAP  32
#define DCAP  32
#define OUTC  1024
#define NCHUNK 128
#define NPER  (NN / NCHUNK)   // 16 n per block
#define BG    4               // b groups
#define BPER  (BB / BG)       // 8 b per block
#define THREADS 1024

// Scratch (device globals: allocation inside kernel_launch is forbidden).
__device__ float g_opart[NCHUNK][BB][OUTC];   // per-chunk o partial sums (16 MB)
__device__ float g_o[BB][NCAP][DCAP];         // current routing output o

__global__ __launch_bounds__(THREADS)
void caps_pass_kernel(const float* __restrict__ u, const float* __restrict__ W,
                      int mode)
{
    __shared__ float u_s[BPER][KK];       // u tile for current n
    __shared__ float sm_b[BPER][NCAP];    // routing logits b[b,i] for current n
    __shared__ float sm_c[BPER][NCAP];    // softmax coefficients

    const int tid  = threadIdx.x;     // output column c = tid (0..1023)
    const int lane = tid & 31;        // j (capsule dim index)
    const int wcap = tid >> 5;        // i (capsule index) == warp id
    const int b0   = blockIdx.x * BPER;
    const int n0   = blockIdx.y * NPER;

    // o from previous iteration, fixed for the whole n-chunk: o[b, i=wcap, j=lane]
    float o_r[BPER];
    if (mode) {
        #pragma unroll
        for (int bl = 0; bl < BPER; bl++)
            o_r[bl] = g_o[b0 + bl][wcap][lane];
    }

    float acc[BPER];
    #pragma unroll
    for (int bl = 0; bl < BPER; bl++) acc[bl] = 0.f;

    for (int nn = 0; nn < NPER; nn++) {
        const int n = n0 + nn;

        __syncthreads();   // previous iteration's u_s reads are done
        if (tid < BPER * KK) {
            int bl = tid >> 4, k = tid & 15;
            u_s[bl][k] = u[((size_t)(b0 + bl) * NN + n) * KK + k];
        }
        __syncthreads();

        // u_hat tile: tile[bl] = sum_k u[b0+bl,n,k] * W[n,k,c]
        const float* Wn = W + (size_t)n * KK * OUTC + tid;
        float tile[BPER];
        #pragma unroll
        for (int bl = 0; bl < BPER; bl++) tile[bl] = 0.f;

        #pragma unroll
        for (int k4 = 0; k4 < KK / 4; k4++) {
            float w0 = Wn[(k4 * 4 + 0) * OUTC];
            float w1 = Wn[(k4 * 4 + 1) * OUTC];
            float w2 = Wn[(k4 * 4 + 2) * OUTC];
            float w3 = Wn[(k4 * 4 + 3) * OUTC];
            #pragma unroll
            for (int bl = 0; bl < BPER; bl++) {
                float4 uv = *reinterpret_cast<const float4*>(&u_s[bl][k4 * 4]);
                tile[bl] = fmaf(uv.x, w0, tile[bl]);
                tile[bl] = fmaf(uv.y, w1, tile[bl]);
                tile[bl] = fmaf(uv.z, w2, tile[bl]);
                tile[bl] = fmaf(uv.w, w3, tile[bl]);
            }
        }

        if (mode) {
            // b[b, i] = sum_j o[b,i,j] * u_hat[b,n,i*32+j]  (warp reduce over j)
            #pragma unroll
            for (int bl = 0; bl < BPER; bl++) {
                float p = o_r[bl] * tile[bl];
                #pragma unroll
                for (int off = 16; off > 0; off >>= 1)
                    p += __shfl_down_sync(0xffffffffu, p, off);
                if (lane == 0) sm_b[bl][wcap] = p;
            }
            __syncthreads();

            // softmax over capsules i (axis=1) for each (b, n): warps 0..BPER-1
            if (tid < BPER * NCAP) {
                int bb = tid >> 5, ii = tid & 31;
                float v = sm_b[bb][ii];
                float m = v;
                #pragma unroll
                for (int off = 16; off > 0; off >>= 1)
                    m = fmaxf(m, __shfl_xor_sync(0xffffffffu, m, off));
                float e = __expf(v - m);
                float s = e;
                #pragma unroll
                for (int off = 16; off > 0; off >>= 1)
                    s += __shfl_xor_sync(0xffffffffu, s, off);
                sm_c[bb][ii] = e / s;
            }
            __syncthreads();

            #pragma unroll
            for (int bl = 0; bl < BPER; bl++)
                acc[bl] = fmaf(sm_c[bl][wcap], tile[bl], acc[bl]);
        } else {
            // uniform c = 1/32 (applied in reduce kernel)
            #pragma unroll
            for (int bl = 0; bl < BPER; bl++) acc[bl] += tile[bl];
        }
    }

    #pragma unroll
    for (int bl = 0; bl < BPER; bl++)
        g_opart[blockIdx.y][b0 + bl][tid] = acc[bl];
}

// Reduce partials over chunks, then l2-normalize (mode 0/1 -> g_o) or squash
// (mode 2 -> out). One block per b, thread = i*32+j.
__global__ __launch_bounds__(OUTC)
void caps_reduce_kernel(float* __restrict__ out, int mode)
{
    const int b   = blockIdx.x;
    const int tid = threadIdx.x;

    float s = 0.f;
    #pragma unroll 8
    for (int ch = 0; ch < NCHUNK; ch++)
        s += g_opart[ch][b][tid];
    if (mode == 0) s *= (1.0f / 32.0f);

    // s2 = sum_j o^2 within each capsule (warp = capsule, lane = j)
    float p = s * s;
    #pragma unroll
    for (int off = 16; off > 0; off >>= 1)
        p += __shfl_xor_sync(0xffffffffu, p, off);

    if (mode < 2) {
        // tf.nn.l2_normalize: x * rsqrt(max(s2, 1e-12))
        g_o[b][tid >> 5][tid & 31] = s * rsqrtf(fmaxf(p, 1e-12f));
    } else {
        // squash: (s2/(1+s2)) * x / sqrt(s2 + 1e-7)
        out[(size_t)b * OUTC + tid] = (p / (1.f + p)) * s * rsqrtf(p + 1e-7f);
    }
}

extern "C" void kernel_launch(void* const* d_in, const int* in_sizes, int n_in,
                              void* d_out, int out_size)
{
    const float* u = (const float*)d_in[0];
    const float* W = (const float*)d_in[1];
    if (n_in >= 2 && in_sizes[0] > in_sizes[1]) {  // defensive: u is the smaller input
        const float* t = u; u = W; W = t;
    }
    float* out = (float*)d_out;

    dim3 grid(BG, NCHUNK);

    // iteration 0: uniform coefficients
    caps_pass_kernel<<<grid, THREADS>>>(u, W, 0);
    caps_reduce_kernel<<<BB, OUTC>>>(out, 0);
    // iteration 1: fused b-compute + softmax + o-accumulate
    caps_pass_kernel<<<grid, THREADS>>>(u, W, 1);
    caps_reduce_kernel<<<BB, OUTC>>>(out, 1);
    // iteration 2: same, final normalize is squash -> d_out
    caps_pass_kernel<<<grid, THREADS>>>(u, W, 1);
    caps_reduce_kernel<<<BB, OUTC>>>(out, 2);
}

// round 2
// speedup vs baseline: 1.7809x; 1.7809x over previous
#include <cuda_runtime.h>

// CapsuleLayer dynamic routing — materialized-u_hat formulation.
//
// Shapes: u [B=32, N=2048, K=16] f32, W [N=2048, K=16, OUTC=1024] f32,
// out [B=32, 32, 32] f32 (=OUTC per b).
//
//  pass0 : u_hat = einsum('bnk,nko->bno') stored to g_uhat (268MB, fp32),
//          plus per-block partial sums of u_hat over n (iteration-0 o, since
//          softmax(0) is uniform).  W is read exactly once (one block spans
//          all 32 b).
//  reduce: sum partials over chunks, l2-normalize -> g_o   (or squash -> out)
//  pass1 : per (b,n): logits b_i = <o[b,i,:], u_hat[b,n,i*32:]>, softmax over
//          i (local in n!), accumulate c_i * u_hat into o partials. Streams
//          g_uhat once (268MB), memory-bound.
//  (pass1 + reduce) x2, final reduce applies squash -> d_out.

#define BB    32
#define NN    2048
#define KK    16
#define OUTC  1024

#define NB0   296          // pass0 blocks (2 waves of 148 SMs)

#define BPER1 4            // pass1: b per block
#define BG1   (BB / BPER1) // 8
#define NCH1  64           // pass1 n-chunks
#define NPER1 (NN / NCH1)  // 32

// ---- scratch (device globals; runtime allocation is forbidden) ----
__device__ float g_uhat[(size_t)BB * NN * OUTC];      // 268 MB
__device__ float g_opart[(size_t)NB0 * BB * OUTC];    // 38.8 MB (pass1 uses first NCH1)
__device__ float g_o[BB * OUTC];                      // current routing output

// ================= pass0: u_hat materialization + iter-0 sum =================
__global__ __launch_bounds__(1024)
void caps_pass0(const float* __restrict__ u, const float* __restrict__ W)
{
    __shared__ float u_s[BB][KK];

    const int tid = threadIdx.x;                 // output column c
    const int n0  = (blockIdx.x * NN) / NB0;
    const int n1  = ((blockIdx.x + 1) * NN) / NB0;

    float acc[BB];
    #pragma unroll
    for (int bl = 0; bl < BB; bl++) acc[bl] = 0.f;

    for (int n = n0; n < n1; n++) {
        __syncthreads();
        if (tid < BB * KK) {
            int bl = tid >> 4, k = tid & 15;
            u_s[bl][k] = u[((size_t)bl * NN + n) * KK + k];
        }
        __syncthreads();

        const float* Wn = W + (size_t)n * KK * OUTC + tid;
        float w[KK];
        #pragma unroll
        for (int k = 0; k < KK; k++) w[k] = Wn[k * OUTC];

        float* uhn = g_uhat + (size_t)n * OUTC + tid;
        #pragma unroll
        for (int bl = 0; bl < BB; bl++) {
            const float4* u4 = reinterpret_cast<const float4*>(u_s[bl]);
            float t = 0.f;
            #pragma unroll
            for (int k4 = 0; k4 < KK / 4; k4++) {
                float4 uv = u4[k4];
                t = fmaf(uv.x, w[k4 * 4 + 0], t);
                t = fmaf(uv.y, w[k4 * 4 + 1], t);
                t = fmaf(uv.z, w[k4 * 4 + 2], t);
                t = fmaf(uv.w, w[k4 * 4 + 3], t);
            }
            uhn[(size_t)bl * NN * OUTC] = t;
            acc[bl] += t;
        }
    }

    #pragma unroll
    for (int bl = 0; bl < BB; bl++)
        g_opart[((size_t)blockIdx.x * BB + bl) * OUTC + tid] = acc[bl];
}

// ================= pass1: fused logits + softmax + o accumulation ============
__global__ __launch_bounds__(1024, 2)
void caps_pass1()
{
    __shared__ float sm_b[BPER1][BB];   // logits over capsules for current n
    __shared__ float sm_c[BPER1][BB];   // softmax coefficients

    const int tid  = threadIdx.x;       // col = i*32 + j
    const int lane = tid & 31;          // j
    const int wcap = tid >> 5;          // i (capsule) == warp id
    const int b0   = blockIdx.x * BPER1;
    const int n0   = blockIdx.y * NPER1;

    float o_r[BPER1], acc[BPER1];
    #pragma unroll
    for (int bl = 0; bl < BPER1; bl++) {
        o_r[bl] = g_o[(b0 + bl) * OUTC + tid];
        acc[bl] = 0.f;
    }

    const float* uh = g_uhat + (size_t)n0 * OUTC + tid;

    // preload first tile
    float cur[BPER1];
    #pragma unroll
    for (int bl = 0; bl < BPER1; bl++)
        cur[bl] = uh[((size_t)(b0 + bl) * NN) * OUTC];

    for (int nn = 0; nn < NPER1; nn++) {
        // logits: b[b,i] = sum_j o[b,i,j] * u_hat  (warp reduce over j)
        #pragma unroll
        for (int bl = 0; bl < BPER1; bl++) {
            float p = o_r[bl] * cur[bl];
            #pragma unroll
            for (int off = 16; off > 0; off >>= 1)
                p += __shfl_down_sync(0xffffffffu, p, off);
            if (lane == 0) sm_b[bl][wcap] = p;
        }

        // prefetch next tile (overlaps the two barriers + softmax)
        float nxt[BPER1];
        if (nn + 1 < NPER1) {
            const float* uhn = uh + (size_t)(nn + 1) * OUTC;
            #pragma unroll
            for (int bl = 0; bl < BPER1; bl++)
                nxt[bl] = uhn[((size_t)(b0 + bl) * NN) * OUTC];
        }

        __syncthreads();

        // softmax over capsules i for each of the BPER1 b's (warps 0..BPER1-1)
        if (tid < BPER1 * 32) {
            int bb = tid >> 5, ii = tid & 31;
            float v = sm_b[bb][ii];
            float m = v;
            #pragma unroll
            for (int off = 16; off > 0; off >>= 1)
                m = fmaxf(m, __shfl_xor_sync(0xffffffffu, m, off));
            float e = __expf(v - m);
            float s = e;
            #pragma unroll
            for (int off = 16; off > 0; off >>= 1)
                s += __shfl_xor_sync(0xffffffffu, s, off);
            sm_c[bb][ii] = e / s;
        }
        __syncthreads();

        #pragma unroll
        for (int bl = 0; bl < BPER1; bl++) {
            acc[bl] = fmaf(sm_c[bl][wcap], cur[bl], acc[bl]);
            cur[bl] = nxt[bl];
        }
    }

    #pragma unroll
    for (int bl = 0; bl < BPER1; bl++)
        g_opart[((size_t)blockIdx.y * BB + (b0 + bl)) * OUTC + tid] = acc[bl];
}

// ================= reduce: sum chunks, normalize / squash =====================
// grid (BB, 8), 128 threads: block covers 128 columns (= 4 capsules) of one b.
__global__ __launch_bounds__(128)
void caps_reduce(float* __restrict__ out, int nch, int mode)
{
    const int b   = blockIdx.x;
    const int col = blockIdx.y * 128 + threadIdx.x;

    const float* p = g_opart + (size_t)b * OUTC + col;
    float s = 0.f;
    int ch = 0;
    #pragma unroll 1
    for (; ch + 8 <= nch; ch += 8) {
        float t0 = p[(size_t)(ch + 0) * BB * OUTC];
        float t1 = p[(size_t)(ch + 1) * BB * OUTC];
        float t2 = p[(size_t)(ch + 2) * BB * OUTC];
        float t3 = p[(size_t)(ch + 3) * BB * OUTC];
        float t4 = p[(size_t)(ch + 4) * BB * OUTC];
        float t5 = p[(size_t)(ch + 5) * BB * OUTC];
        float t6 = p[(size_t)(ch + 6) * BB * OUTC];
        float t7 = p[(size_t)(ch + 7) * BB * OUTC];
        s += ((t0 + t1) + (t2 + t3)) + ((t4 + t5) + (t6 + t7));
    }
    for (; ch < nch; ch++) s += p[(size_t)ch * BB * OUTC];

    if (mode == 0) s *= (1.0f / 32.0f);

    // per-capsule squared norm: warp == capsule (block y*128 is 32-aligned)
    float q = s * s;
    #pragma unroll
    for (int off = 16; off > 0; off >>= 1)
        q += __shfl_xor_sync(0xffffffffu, q, off);

    if (mode < 2) {
        g_o[b * OUTC + col] = s * rsqrtf(fmaxf(q, 1e-12f));        // l2_normalize
    } else {
        out[(size_t)b * OUTC + col] = (q / (1.f + q)) * s * rsqrtf(q + 1e-7f); // squash
    }
}

extern "C" void kernel_launch(void* const* d_in, const int* in_sizes, int n_in,
                              void* d_out, int out_size)
{
    const float* u = (const float*)d_in[0];
    const float* W = (const float*)d_in[1];
    if (n_in >= 2 && in_sizes[0] > in_sizes[1]) {  // defensive: u is the smaller input
        const float* t = u; u = W; W = t;
    }
    float* out = (float*)d_out;

    dim3 rgrid(BB, 8);

    caps_pass0<<<NB0, 1024>>>(u, W);
    caps_reduce<<<rgrid, 128>>>(out, NB0, 0);

    caps_pass1<<<dim3(BG1, NCH1), 1024>>>();
    caps_reduce<<<rgrid, 128>>>(out, NCH1, 1);

    caps_pass1<<<dim3(BG1, NCH1), 1024>>>();
    caps_reduce<<<rgrid, 128>>>(out, NCH1, 2);
}

// round 5
// speedup vs baseline: 2.0290x; 1.1393x over previous
#include <cuda_runtime.h>

// CapsuleLayer dynamic routing — materialized-u_hat, barrier-free GEMM pass.
// u [32,2048,16] f32, W [2048,16,1024] f32, out [32,1024] f32.

#define BB    32
#define NN    2048
#define KK    16
#define OUTC  1024

#define P0_CG 8     // pass0 c-groups (128 c each)
#define P0_NC 18    // pass0 n-chunks  -> 144 blocks, one wave
#define P1_NC 28    // pass1 n-chunks  -> 16*28 = 448 blocks @ occ 3

// ---- scratch (device globals; runtime allocation is forbidden) ----
__device__ float g_uhat[(size_t)BB * NN * OUTC];   // 268 MB
__device__ float g_opart[32 * BB * OUTC];          // 4 MB partials
__device__ float g_o[BB * OUTC];                   // current routing output

__device__ __forceinline__ void ffma2(unsigned long long& d,
                                      unsigned long long a, unsigned long long b) {
    asm("fma.rn.f32x2 %0, %1, %2, %0;" : "+l"(d) : "l"(a), "l"(b));
}
__device__ __forceinline__ void fadd2(unsigned long long& d, unsigned long long a) {
    asm("add.rn.f32x2 %0, %0, %1;" : "+l"(d) : "l"(a));
}
__device__ __forceinline__ unsigned long long dup2(float x) {
    unsigned long long r;
    asm("mov.b64 %0, {%1, %1};" : "=l"(r) : "f"(x));
    return r;
}

// ============ pass0: u_hat = u @ W, plus iteration-0 partial sums ============
// warp = b (32 warps), lane = 4 consecutive c. No smem, no barriers.
// All vector pointers are in 16-byte (float4 / ulonglong2) units:
//   one row of OUTC floats = OUTC/4 = 256 vector elements.
#define ROWV (OUTC / 4)   // 256

__global__ __launch_bounds__(1024, 1)
void caps_pass0(const float* __restrict__ u, const float* __restrict__ W)
{
    const int lane = threadIdx.x & 31;
    const int b    = threadIdx.x >> 5;              // warp id == b
    const int cv   = blockIdx.x * 32 + lane;        // vector-column (4 floats)
    const int n0   = (blockIdx.y * NN) / P0_NC;
    const int n1   = ((blockIdx.y + 1) * NN) / P0_NC;

    unsigned long long acc01 = 0ull, acc23 = 0ull;   // f32x2 accumulators

    const float* ub = u + (size_t)b * NN * KK;
    ulonglong2* uh = reinterpret_cast<ulonglong2*>(g_uhat)
                   + (size_t)b * NN * ROWV + cv;
    const ulonglong2* Wv = reinterpret_cast<const ulonglong2*>(W) + cv;

    for (int n = n0; n < n1; n++) {
        float uu = (lane < KK) ? ub[(size_t)n * KK + lane] : 0.f;

        const ulonglong2* Wn = Wv + (size_t)n * KK * ROWV;

        unsigned long long t01 = 0ull, t23 = 0ull;
        #pragma unroll
        for (int k4 = 0; k4 < KK / 4; k4++) {
            ulonglong2 w0 = Wn[(size_t)(k4 * 4 + 0) * ROWV];
            ulonglong2 w1 = Wn[(size_t)(k4 * 4 + 1) * ROWV];
            ulonglong2 w2 = Wn[(size_t)(k4 * 4 + 2) * ROWV];
            ulonglong2 w3 = Wn[(size_t)(k4 * 4 + 3) * ROWV];
            unsigned long long u0 = dup2(__shfl_sync(0xffffffffu, uu, k4 * 4 + 0));
            unsigned long long u1 = dup2(__shfl_sync(0xffffffffu, uu, k4 * 4 + 1));
            unsigned long long u2 = dup2(__shfl_sync(0xffffffffu, uu, k4 * 4 + 2));
            unsigned long long u3 = dup2(__shfl_sync(0xffffffffu, uu, k4 * 4 + 3));
            ffma2(t01, u0, w0.x); ffma2(t23, u0, w0.y);
            ffma2(t01, u1, w1.x); ffma2(t23, u1, w1.y);
            ffma2(t01, u2, w2.x); ffma2(t23, u2, w2.y);
            ffma2(t01, u3, w3.x); ffma2(t23, u3, w3.y);
        }

        ulonglong2 st; st.x = t01; st.y = t23;
        uh[(size_t)n * ROWV] = st;
        fadd2(acc01, t01);
        fadd2(acc23, t23);
    }

    ulonglong2 sa; sa.x = acc01; sa.y = acc23;
    reinterpret_cast<ulonglong2*>(g_opart)
        [(size_t)(blockIdx.y * BB + b) * ROWV + cv] = sa;
}

// ====== pass1: fused logits + softmax(capsule axis) + o accumulation ========
// 512 threads: 2 b's x 256 c-threads (4 consecutive c each).
__global__ __launch_bounds__(512, 3)
void caps_pass1()
{
    __shared__ float sm_b[2][BB];
    __shared__ float sm_c[2][BB];

    const int tid = threadIdx.x;
    const int bl  = tid >> 8;          // 0..1
    const int ct  = tid & 255;         // c-thread (vector column)
    const int c   = ct * 4;
    const int i   = ct >> 3;           // capsule (8 threads per capsule)
    const int b   = blockIdx.x * 2 + bl;

    const int n0  = (blockIdx.y * NN) / P1_NC;
    const int n1  = ((blockIdx.y + 1) * NN) / P1_NC;
    const int cnt = n1 - n0;

    float4 o4 = *reinterpret_cast<const float4*>(g_o + b * OUTC + c);
    float4 acc4 = make_float4(0.f, 0.f, 0.f, 0.f);

    const float4* base = reinterpret_cast<const float4*>(g_uhat)
                       + ((size_t)b * NN + n0) * ROWV + ct;

    float4 buf0 = base[0];
    float4 buf1 = (cnt > 1) ? base[ROWV] : buf0;

    for (int idx = 0; idx < cnt; idx++) {
        float4 cur = buf0;
        buf0 = buf1;
        if (idx + 2 < cnt) buf1 = base[(size_t)(idx + 2) * ROWV];

        // logit partial over this thread's 4 j's, then reduce over 8 threads
        float p = cur.x * o4.x + cur.y * o4.y + cur.z * o4.z + cur.w * o4.w;
        p += __shfl_down_sync(0xffffffffu, p, 4);
        p += __shfl_down_sync(0xffffffffu, p, 2);
        p += __shfl_down_sync(0xffffffffu, p, 1);
        if ((ct & 7) == 0) sm_b[bl][i] = p;
        __syncthreads();

        // softmax over capsules for the 2 b's (warps 0 and 1)
        if (tid < 64) {
            int bb = tid >> 5, ii = tid & 31;
            float v = sm_b[bb][ii];
            float m = v;
            #pragma unroll
            for (int off = 16; off > 0; off >>= 1)
                m = fmaxf(m, __shfl_xor_sync(0xffffffffu, m, off));
            float e = __expf(v - m);
            float s = e;
            #pragma unroll
            for (int off = 16; off > 0; off >>= 1)
                s += __shfl_xor_sync(0xffffffffu, s, off);
            sm_c[bb][ii] = e / s;
        }
        __syncthreads();

        float ci = sm_c[bl][i];
        acc4.x = fmaf(ci, cur.x, acc4.x);
        acc4.y = fmaf(ci, cur.y, acc4.y);
        acc4.z = fmaf(ci, cur.z, acc4.z);
        acc4.w = fmaf(ci, cur.w, acc4.w);
    }

    reinterpret_cast<float4*>(g_opart)
        [(size_t)(blockIdx.y * BB + b) * ROWV + ct] = acc4;
}

// ============ reduce: sum chunks, l2-normalize (->g_o) or squash (->out) =====
__global__ __launch_bounds__(128)
void caps_reduce(float* __restrict__ out, int nch, int mode)
{
    const int b   = blockIdx.x;
    const int col = blockIdx.y * 128 + threadIdx.x;

    const float* p = g_opart + (size_t)b * OUTC + col;
    float s = 0.f;
    int ch = 0;
    #pragma unroll 1
    for (; ch + 6 <= nch; ch += 6) {
        float t0 = p[(size_t)(ch + 0) * BB * OUTC];
        float t1 = p[(size_t)(ch + 1) * BB * OUTC];
        float t2 = p[(size_t)(ch + 2) * BB * OUTC];
        float t3 = p[(size_t)(ch + 3) * BB * OUTC];
        float t4 = p[(size_t)(ch + 4) * BB * OUTC];
        float t5 = p[(size_t)(ch + 5) * BB * OUTC];
        s += ((t0 + t1) + (t2 + t3)) + (t4 + t5);
    }
    for (; ch < nch; ch++) s += p[(size_t)ch * BB * OUTC];

    if (mode == 0) s *= (1.0f / 32.0f);

    float q = s * s;
    #pragma unroll
    for (int off = 16; off > 0; off >>= 1)
        q += __shfl_xor_sync(0xffffffffu, q, off);

    if (mode < 2) {
        g_o[b * OUTC + col] = s * rsqrtf(fmaxf(q, 1e-12f));            // l2_normalize
    } else {
        out[(size_t)b * OUTC + col] = (q / (1.f + q)) * s * rsqrtf(q + 1e-7f);  // squash
    }
}

extern "C" void kernel_launch(void* const* d_in, const int* in_sizes, int n_in,
                              void* d_out, int out_size)
{
    const float* u = (const float*)d_in[0];
    const float* W = (const float*)d_in[1];
    if (n_in >= 2 && in_sizes[0] > in_sizes[1]) {  // defensive: u is the smaller input
        const float* t = u; u = W; W = t;
    }
    float* out = (float*)d_out;

    dim3 rgrid(BB, 8);

    caps_pass0<<<dim3(P0_CG, P0_NC), 1024>>>(u, W);
    caps_reduce<<<rgrid, 128>>>(out, P0_NC, 0);

    caps_pass1<<<dim3(BB / 2, P1_NC), 512>>>();
    caps_reduce<<<rgrid, 128>>>(out, P1_NC, 1);

    caps_pass1<<<dim3(BB / 2, P1_NC), 512>>>();
    caps_reduce<<<rgrid, 128>>>(out, P1_NC, 2);
}